// round 17
// baseline (speedup 1.0000x reference)
#include <cuda_runtime.h>
#include <cuda_fp16.h>
#include <cstdint>
#include <cstddef>

// Problem shape (fixed)
#define Bc 2
#define Hc 16
#define Sc 2048
#define Dc 64
#define NELEM  (Bc * Hc * Sc * Dc)   // 4194304
#define NELEM2 (NELEM / 2)

// Tiling
#define BM 128            // q rows per CTA
#define BK 64             // keys per tile
#define NT (Sc / BK)      // 32 tiles
#define PH 72             // fp16 smem pitch (halfs); 144B rows -> conflict-free ldmatrix

// SMEM layout (bytes)
#define SM_Q   0
#define SMQB   (BM * PH * 2)          // 18432
#define KVB    (BK * PH * 2)          // 9216 (one K or V tile)
#define STB    (2 * KVB)              // 18432 per stage (K + V)
#define NSTG   3
#define SM_TOT (SMQB + NSTG * STB)    // 73728  -> 3 CTAs/SM (221KB)

// fp16 scratch (pre-converted inputs)
__device__ __align__(16) __half2 QH[NELEM2];
__device__ __align__(16) __half2 KH[NELEM2];
__device__ __align__(16) __half2 VH[NELEM2];

__global__ void cvt_f2h(const float2* __restrict__ q,
                        const float2* __restrict__ k,
                        const float2* __restrict__ v)
{
    int i = blockIdx.x * 256 + threadIdx.x;
    float2 a = q[i]; QH[i] = __floats2half2_rn(a.x, a.y);
    float2 b = k[i]; KH[i] = __floats2half2_rn(b.x, b.y);
    float2 c = v[i]; VH[i] = __floats2half2_rn(c.x, c.y);
}

static __device__ __forceinline__ uint32_t smem_u32(const void* p) {
    uint32_t a;
    asm("{ .reg .u64 t; cvta.to.shared.u64 t, %1; cvt.u32.u64 %0, t; }"
        : "=r"(a) : "l"(p));
    return a;
}
static __device__ __forceinline__ void mma_f16(float c[4],
                                               uint32_t a0, uint32_t a1, uint32_t a2, uint32_t a3,
                                               uint32_t b0, uint32_t b1) {
    asm volatile(
        "mma.sync.aligned.m16n8k16.row.col.f32.f16.f16.f32 "
        "{%0,%1,%2,%3}, {%4,%5,%6,%7}, {%8,%9}, {%0,%1,%2,%3};"
        : "+f"(c[0]), "+f"(c[1]), "+f"(c[2]), "+f"(c[3])
        : "r"(a0), "r"(a1), "r"(a2), "r"(a3), "r"(b0), "r"(b1));
}
static __device__ __forceinline__ void ldsm4(uint32_t& r0, uint32_t& r1,
                                             uint32_t& r2, uint32_t& r3, uint32_t a) {
    asm volatile("ldmatrix.sync.aligned.m8n8.x4.shared.b16 {%0,%1,%2,%3}, [%4];"
                 : "=r"(r0), "=r"(r1), "=r"(r2), "=r"(r3) : "r"(a));
}
static __device__ __forceinline__ void ldsm4t(uint32_t& r0, uint32_t& r1,
                                              uint32_t& r2, uint32_t& r3, uint32_t a) {
    asm volatile("ldmatrix.sync.aligned.m8n8.x4.trans.shared.b16 {%0,%1,%2,%3}, [%4];"
                 : "=r"(r0), "=r"(r1), "=r"(r2), "=r"(r3) : "r"(a));
}
static __device__ __forceinline__ void cp16(uint32_t dst, const void* src) {
    asm volatile("cp.async.cg.shared.global [%0], [%1], 16;"
                 :: "r"(dst), "l"(src) : "memory");
}

__global__ __launch_bounds__(256, 3)
void fra_f16_kernel(const float* __restrict__ mask, float* __restrict__ o)
{
    extern __shared__ char smem[];
    const uint32_t sb = smem_u32(smem);
    const int tid  = threadIdx.x;
    const int lane = tid & 31;
    const int wid  = tid >> 5;
    const int gid  = lane >> 2;
    const int tig  = lane & 3;
    const int mbase = wid * 16;            // warp's 16-row strip
    const int bh = blockIdx.y;
    const int q0 = blockIdx.x * BM;

    const __half* qh = (const __half*)QH + (size_t)bh * Sc * Dc;
    const __half* kh = (const __half*)KH + (size_t)bh * Sc * Dc;
    const __half* vh = (const __half*)VH + (size_t)bh * Sc * Dc;
    const float*  mg = mask + (size_t)bh * Sc * Sc;
    float*        og = o    + (size_t)bh * Sc * Dc;

    // ---- prologue: cp.async Q + tile0 (group A), tile1 (group B) ----
    {
        #pragma unroll
        for (int i = 0; i < 4; i++) {
            int fi = tid + i * 256;
            int r = fi >> 3, c8 = fi & 7;
            cp16(sb + SM_Q + (uint32_t)(r * PH + c8 * 8) * 2,
                 qh + (size_t)(q0 + r) * Dc + c8 * 8);
        }
        #pragma unroll
        for (int i = 0; i < 2; i++) {
            int fi = tid + i * 256;
            int r = fi >> 3, c8 = fi & 7;
            cp16(sb + SMQB + (uint32_t)(r * PH + c8 * 8) * 2,
                 kh + (size_t)r * Dc + c8 * 8);
            cp16(sb + SMQB + KVB + (uint32_t)(r * PH + c8 * 8) * 2,
                 vh + (size_t)r * Dc + c8 * 8);
        }
        asm volatile("cp.async.commit_group;" ::: "memory");
        #pragma unroll
        for (int i = 0; i < 2; i++) {
            int fi = tid + i * 256;
            int r = fi >> 3, c8 = fi & 7;
            cp16(sb + SMQB + STB + (uint32_t)(r * PH + c8 * 8) * 2,
                 kh + (size_t)(BK + r) * Dc + c8 * 8);
            cp16(sb + SMQB + STB + KVB + (uint32_t)(r * PH + c8 * 8) * 2,
                 vh + (size_t)(BK + r) * Dc + c8 * 8);
        }
        asm volatile("cp.async.commit_group;" ::: "memory");
    }

    // per-lane fragment address components
    const int qrow  = (lane & 7) + 8 * ((lane >> 3) & 1);   // A / V-trans row pattern
    const int qcol8 = 8 * (lane >> 4);
    const int krow  = (lane & 7) + 8 * (lane >> 4);          // K B-frag row pattern
    const int kcolb = 8 * ((lane >> 3) & 1);
    const uint32_t aQ = sb + SM_Q + (uint32_t)((mbase + qrow) * PH + qcol8) * 2;

    float oacc[8][4];
    #pragma unroll
    for (int d = 0; d < 8; d++)
        #pragma unroll
        for (int r = 0; r < 4; r++) oacc[d][r] = 0.0f;
    float racc0 = 0.0f, racc1 = 0.0f;

    const float* mr0 = mg + (size_t)(q0 + mbase + gid) * Sc + 2 * tig;
    const float* mr1 = mr0 + (size_t)8 * Sc;

    for (int tt = 0; tt < NT; tt++) {
        const int t = tt * BK;

        // wait for tile tt (allow the most recent group to stay pending)
        if (tt + 1 < NT) {
            asm volatile("cp.async.wait_group 1;" ::: "memory");
        } else {
            asm volatile("cp.async.wait_group 0;" ::: "memory");
        }
        // Barrier seals all reads of iter tt-1 — AFTER it, recycling stage
        // (tt+2)%3 == (tt-1)%3 below is race-free.
        __syncthreads();

        // issue tile tt+2 into stage (tt+2)%3 (post-barrier => safe)
        if (tt + 2 < NT) {
            const uint32_t stb = sb + SMQB + (uint32_t)((tt + 2) % NSTG) * STB;
            #pragma unroll
            for (int i = 0; i < 2; i++) {
                int fi = tid + i * 256;
                int r = fi >> 3, c8 = fi & 7;
                cp16(stb + (uint32_t)(r * PH + c8 * 8) * 2,
                     kh + (size_t)(t + 2 * BK + r) * Dc + c8 * 8);
                cp16(stb + KVB + (uint32_t)(r * PH + c8 * 8) * 2,
                     vh + (size_t)(t + 2 * BK + r) * Dc + c8 * 8);
            }
            asm volatile("cp.async.commit_group;" ::: "memory");
        }

        const uint32_t kbs = sb + SMQB + (uint32_t)(tt % NSTG) * STB;
        const uint32_t vbs = kbs + KVB;

        // ---- fused per-key-group pipeline: GEMM1(p) -> mask -> GEMM2(p) ----
        #pragma unroll
        for (int p = 0; p < 4; p++) {
            // mask loads for score cols 16p..16p+15 (issued early, consumed post-GEMM1)
            const int c0 = 8 * (2 * p), c1 = 8 * (2 * p + 1);
            float2 m00 = *(const float2*)(mr0 + t + c0);
            float2 m01 = *(const float2*)(mr1 + t + c0);
            float2 m10 = *(const float2*)(mr0 + t + c1);
            float2 m11 = *(const float2*)(mr1 + t + c1);

            // GEMM1: S(16x16) for this key group
            float s0[4] = {0.f, 0.f, 0.f, 0.f};
            float s1[4] = {0.f, 0.f, 0.f, 0.f};
            #pragma unroll
            for (int kk = 0; kk < 4; kk++) {
                uint32_t a0, a1, a2, a3, b0, b1, b2, b3;
                ldsm4(a0, a1, a2, a3, aQ + (uint32_t)kk * 32);
                ldsm4(b0, b1, b2, b3,
                      kbs + (uint32_t)((16 * p + krow) * PH + kk * 16 + kcolb) * 2);
                mma_f16(s0, a0, a1, a2, a3, b0, b1);
                mma_f16(s1, a0, a1, a2, a3, b2, b3);
            }

            // mask + abs-sum + pack P-frags for this group
            float t0 = s0[0] * m00.x, t1 = s0[1] * m00.y;
            float t2 = s0[2] * m01.x, t3 = s0[3] * m01.y;
            float u0 = s1[0] * m10.x, u1 = s1[1] * m10.y;
            float u2 = s1[2] * m11.x, u3 = s1[3] * m11.y;
            racc0 += fabsf(t0) + fabsf(t1) + fabsf(u0) + fabsf(u1);
            racc1 += fabsf(t2) + fabsf(t3) + fabsf(u2) + fabsf(u3);
            __half2 h0 = __floats2half2_rn(t0, t1);
            __half2 h1 = __floats2half2_rn(t2, t3);
            __half2 h2 = __floats2half2_rn(u0, u1);
            __half2 h3 = __floats2half2_rn(u2, u3);
            uint32_t pa0 = *(uint32_t*)&h0, pa1 = *(uint32_t*)&h1;
            uint32_t pa2 = *(uint32_t*)&h2, pa3 = *(uint32_t*)&h3;

            // GEMM2: O += P(16 keys of group p) @ V
            #pragma unroll
            for (int d = 0; d < 4; d++) {
                uint32_t b0, b1, b2, b3;
                ldsm4t(b0, b1, b2, b3,
                       vbs + (uint32_t)((16 * p + qrow) * PH + 16 * d + qcol8) * 2);
                mma_f16(oacc[2 * d],     pa0, pa1, pa2, pa3, b0, b1);
                mma_f16(oacc[2 * d + 1], pa0, pa1, pa2, pa3, b2, b3);
            }
        }
        // no bottom barrier
    }

    // ---- warp-local row abs-sums (warp owns full rows) ----
    racc0 += __shfl_xor_sync(0xffffffffu, racc0, 1);
    racc0 += __shfl_xor_sync(0xffffffffu, racc0, 2);
    racc1 += __shfl_xor_sync(0xffffffffu, racc1, 1);
    racc1 += __shfl_xor_sync(0xffffffffu, racc1, 2);
    const float rinv0 = 1.0f / fmaxf(racc0, 1.0f);
    const float rinv1 = 1.0f / fmaxf(racc1, 1.0f);

    float* or0 = og + (size_t)(q0 + mbase + gid) * Dc;
    float* or1 = or0 + (size_t)8 * Dc;
    #pragma unroll
    for (int db = 0; db < 8; db++) {
        const int col = 8 * db + 2 * tig;
        float2 y0, y1;
        y0.x = oacc[db][0] * rinv0; y0.y = oacc[db][1] * rinv0;
        y1.x = oacc[db][2] * rinv1; y1.y = oacc[db][3] * rinv1;
        *(float2*)(or0 + col) = y0;
        *(float2*)(or1 + col) = y1;
    }
}

extern "C" void kernel_launch(void* const* d_in, const int* in_sizes, int n_in,
                              void* d_out, int out_size)
{
    (void)in_sizes; (void)n_in; (void)out_size;
    const float* q    = (const float*)d_in[0];
    const float* k    = (const float*)d_in[1];
    const float* v    = (const float*)d_in[2];
    const float* mask = (const float*)d_in[3];
    float* o = (float*)d_out;

    // pre-convert q/k/v to fp16 scratch
    cvt_f2h<<<NELEM2 / 256, 256>>>((const float2*)q, (const float2*)k, (const float2*)v);

    cudaFuncSetAttribute(fra_f16_kernel,
                         cudaFuncAttributeMaxDynamicSharedMemorySize, SM_TOT);
    dim3 grid(Sc / BM, Bc * Hc);   // (16, 32)
    fra_f16_kernel<<<grid, 256, SM_TOT>>>(mask, o);
}